// round 13
// baseline (speedup 1.0000x reference)
#include <cuda_runtime.h>
#include <cuda_bf16.h>
#include <math.h>

#define BSZ 16
#define CW  32
#define MY  180
#define NX  360
#define KM  32
#define PLANE (MY*NX)
#define PIX (BSZ*PLANE)

__device__ __forceinline__ float geluf(float x) {
    return 0.5f * x * (1.0f + erff(x * 0.70710678118654752f));
}

__device__ __forceinline__ void cpa16(void* dst, const void* src, int szbytes) {
    unsigned d = (unsigned)__cvta_generic_to_shared(dst);
    asm volatile("cp.async.cg.shared.global [%0], [%1], 16, %2;"
                 :: "r"(d), "l"(src), "r"(szbytes) : "memory");
}
#define CPA_COMMIT() asm volatile("cp.async.commit_group;" ::: "memory")
#define CPA_WAIT0()  asm volatile("cp.async.wait_group 0;" ::: "memory")
#define CPA_WAIT1()  asm volatile("cp.async.wait_group 1;" ::: "memory")

// m16n8k16 bf16 MMA, fp32 accum
__device__ __forceinline__ void mma16816(float* d, const unsigned* a, const unsigned* b) {
    asm volatile(
        "mma.sync.aligned.m16n8k16.row.col.f32.bf16.bf16.f32 "
        "{%0,%1,%2,%3},{%4,%5,%6,%7},{%8,%9},{%0,%1,%2,%3};"
        : "+f"(d[0]), "+f"(d[1]), "+f"(d[2]), "+f"(d[3])
        : "r"(a[0]), "r"(a[1]), "r"(a[2]), "r"(a[3]), "r"(b[0]), "r"(b[1]));
}

__device__ __forceinline__ void bsplit(float v, __nv_bfloat16& h, __nv_bfloat16& l) {
    h = __float2bfloat16(v);
    l = __float2bfloat16(v - __bfloat162float(h));
}

// ---------------- device scratch ----------------
__device__ __align__(16) float g_h  [BSZ*CW*PLANE];
__device__ __align__(16) float g_x1 [BSZ*CW*PLANE];
__device__ __align__(16) float g_ftyr[BSZ*CW*KM*NX];
__device__ __align__(16) float g_ftyi[BSZ*CW*KM*NX];
__device__ __align__(16) float g_ftxr[BSZ*CW*KM*MY];
__device__ __align__(16) float g_ftxi[BSZ*CW*KM*MY];
// bf16-split stacked V matrices for forward transforms (rows 0..31 real, 32..63 imag)
#define KPY 192
#define KPX 384
__device__ __align__(16) __nv_bfloat16 g_Vych[64*KPY], g_Vycl[64*KPY];
__device__ __align__(16) __nv_bfloat16 g_Vxch[64*KPX], g_Vxcl[64*KPX];
// bf16-split operands for inverse GEMM:
//   A-part: VyT [m(192)][64]  (k<32: real, k>=32: imag);  OxT [bo][m(192)][64]
//   B-part: OyT [bo][n(384)][64];  VxT [n(384)][64]
__device__ __align__(16) __nv_bfloat16 g_VyTh[192*64], g_VyTl[192*64];
__device__ __align__(16) __nv_bfloat16 g_VxTh[384*64], g_VxTl[384*64];
__device__ __align__(16) __nv_bfloat16 g_oyTh[(size_t)BSZ*CW*384*64], g_oyTl[(size_t)BSZ*CW*384*64];
__device__ __align__(16) __nv_bfloat16 g_oxTh[(size_t)BSZ*CW*192*64], g_oxTl[(size_t)BSZ*CW*192*64];
__device__ float g_gx[NX], g_gy[MY];

// ---------------- precompute ----------------
__global__ void precomputeK(const float* __restrict__ sx,
                            const float* __restrict__ sy) {
    int t = blockIdx.x * blockDim.x + threadIdx.x;
    int stride = gridDim.x * blockDim.x;
    float x0 = sx[0], xL = sx[NX - 1];
    float y0 = sy[0], yL = sy[MY - 1];
    float invRX = 1.0f / (xL - x0), invRY = 1.0f / (yL - y0);
    float invSqN = rsqrtf((float)NX), invSqM = rsqrtf((float)MY);
    const float TWO_PI = 6.283185307179586f;
    __nv_bfloat16 z16 = __float2bfloat16(0.f);

    // zero padded tails of forward V
    for (int idx = t; idx < 64 * (KPY - MY); idx += stride) {
        int r = idx / (KPY - MY), m = MY + idx % (KPY - MY);
        g_Vych[r * KPY + m] = z16; g_Vycl[r * KPY + m] = z16;
    }
    for (int idx = t; idx < 64 * (KPX - NX); idx += stride) {
        int r = idx / (KPX - NX), n = NX + idx % (KPX - NX);
        g_Vxch[r * KPX + n] = z16; g_Vxcl[r * KPX + n] = z16;
    }

    for (int idx = t; idx < KM * NX; idx += stride) {
        int k = idx / NX, n = idx % NX;
        float p = (sx[n] - x0) * invRX;
        float s, c; sincosf(-TWO_PI * (float)k * p, &s, &c);
        float vr = c * invSqN, vi = s * invSqN;
        __nv_bfloat16 h16, l16;
        bsplit(vr, h16, l16);
        g_Vxch[k * KPX + n] = h16; g_Vxcl[k * KPX + n] = l16;
        bsplit(vi, h16, l16);
        g_Vxch[(k + 32) * KPX + n] = h16; g_Vxcl[(k + 32) * KPX + n] = l16;
    }
    for (int idx = t; idx < KM * MY; idx += stride) {
        int k = idx / MY, m = idx % MY;
        float p = (sy[m] - y0) * invRY;
        float s, c; sincosf(-TWO_PI * (float)k * p, &s, &c);
        float vr = c * invSqM, vi = s * invSqM;
        __nv_bfloat16 h16, l16;
        bsplit(vr, h16, l16);
        g_Vych[k * KPY + m] = h16; g_Vycl[k * KPY + m] = l16;
        bsplit(vi, h16, l16);
        g_Vych[(k + 32) * KPY + m] = h16; g_Vycl[(k + 32) * KPY + m] = l16;
    }
    // transposed split V for inverse GEMM
    for (int idx = t; idx < 192 * 64; idx += stride) {
        int m = idx >> 6, k = idx & 63;
        float val = 0.f;
        if (m < MY) {
            float p = (sy[m] - y0) * invRY;
            float s, c; sincosf(-TWO_PI * (float)(k & 31) * p, &s, &c);
            val = (k < 32 ? c : s) * invSqM;
        }
        __nv_bfloat16 h16, l16; bsplit(val, h16, l16);
        g_VyTh[idx] = h16; g_VyTl[idx] = l16;
    }
    for (int idx = t; idx < 384 * 64; idx += stride) {
        int n = idx >> 6, k = idx & 63;
        float val = 0.f;
        if (n < NX) {
            float p = (sx[n] - x0) * invRX;
            float s, c; sincosf(-TWO_PI * (float)(k & 31) * p, &s, &c);
            val = (k < 32 ? c : s) * invSqN;
        }
        __nv_bfloat16 h16, l16; bsplit(val, h16, l16);
        g_VxTh[idx] = h16; g_VxTl[idx] = l16;
    }
    for (int n = t; n < NX; n += stride) g_gx[n] = (sx[n] - x0) / xL;
    for (int m = t; m < MY; m += stride) g_gy[m] = (sy[m] - y0) / yL;
}

// ---------------- fc0 ----------------
__global__ void fc0K(const float* __restrict__ x,
                     const float* __restrict__ w,
                     const float* __restrict__ bias) {
    __shared__ float sX[18][128];
    __shared__ float sW[18][32];
    __shared__ float sB[32];
    int tid = threadIdx.x;
    for (int idx = tid; idx < 18 * 32; idx += 256) sW[idx >> 5][idx & 31] = w[idx];
    if (tid < 32) sB[tid] = bias[tid];

    int p0 = blockIdx.x * 128;
    {
        int pp = tid & 127, hf = tid >> 7;
        int p = p0 + pp;
        const float4* xp = (const float4*)(x + (size_t)p * 16) + hf * 2;
        float4 a = xp[0], b4 = xp[1];
        int c0 = hf * 8;
        sX[c0 + 0][pp] = a.x;  sX[c0 + 1][pp] = a.y;
        sX[c0 + 2][pp] = a.z;  sX[c0 + 3][pp] = a.w;
        sX[c0 + 4][pp] = b4.x; sX[c0 + 5][pp] = b4.y;
        sX[c0 + 6][pp] = b4.z; sX[c0 + 7][pp] = b4.w;
        if (hf == 0) {
            int mn = p % PLANE;
            sX[16][pp] = g_gx[mn % NX];
            sX[17][pp] = g_gy[mn / NX];
        }
    }
    __syncthreads();

    int og = tid >> 5, pg = tid & 31;
    float t[4][4];
#pragma unroll
    for (int a = 0; a < 4; a++) {
        float bb = sB[og * 4 + a];
#pragma unroll
        for (int j = 0; j < 4; j++) t[a][j] = bb;
    }

#pragma unroll 2
    for (int c = 0; c < 18; c++) {
        float4 x4 = *(const float4*)&sX[c][pg * 4];
        float xv[4] = {x4.x, x4.y, x4.z, x4.w};
        float4 w4 = *(const float4*)&sW[c][og * 4];
        float wv[4] = {w4.x, w4.y, w4.z, w4.w};
#pragma unroll
        for (int a = 0; a < 4; a++)
#pragma unroll
            for (int j = 0; j < 4; j++) t[a][j] = fmaf(wv[a], xv[j], t[a][j]);
    }
#pragma unroll
    for (int a = 0; a < 4; a++) {
        int o = og * 4 + a;
#pragma unroll
        for (int j = 0; j < 4; j++) {
            int p = p0 + pg * 4 + j;
            int b = p / PLANE, mn = p % PLANE;
            g_h[((size_t)b * CW + o) * PLANE + mn] = t[a][j];
        }
    }
}

// ---------------- tensor-core forward transforms (unchanged from R12) ----------------
__global__ void __launch_bounds__(256) ftK() {
    int bi = blockIdx.y;
    int tid = threadIdx.x;
    int lane = tid & 31, wid = tid >> 5;
    int wrow = (wid & 1) * 32;
    int wcol = (wid >> 1) * 32;
    const float* hb = g_h + (size_t)bi * PLANE;

    __shared__ __align__(16) char sBuf[12288];
    __nv_bfloat16* sVh = (__nv_bfloat16*)sBuf;
    __nv_bfloat16* sVl = (__nv_bfloat16*)(sBuf + 2048);
    __nv_bfloat16* sXh = (__nv_bfloat16*)(sBuf + 4096);
    __nv_bfloat16* sXl = (__nv_bfloat16*)(sBuf + 8192);

    int isY = (blockIdx.x < 3);
    int c0out = isY ? blockIdx.x * 128 : (blockIdx.x - 3) * 128;
    int nChunks = isY ? (KPY / 16) : (KPX / 16);
    int Lout = isY ? NX : MY;
    const unsigned* gVh = (const unsigned*)(isY ? g_Vych : g_Vxch);
    const unsigned* gVl = (const unsigned*)(isY ? g_Vycl : g_Vxcl);
    int vstride = (isY ? KPY : KPX) >> 1;

    float d[2][4][4];
#pragma unroll
    for (int rt = 0; rt < 2; rt++)
#pragma unroll
        for (int c = 0; c < 4; c++)
#pragma unroll
            for (int j = 0; j < 4; j++) d[rt][c][j] = 0.f;

    for (int kc = 0; kc < nChunks; kc++) {
        int k0 = kc * 16;
        for (int idx = tid; idx < 512; idx += 256) {
            int r = idx >> 3, w = idx & 7;
            ((unsigned*)sVh)[idx] = gVh[r * vstride + (k0 >> 1) + w];
            ((unsigned*)sVl)[idx] = gVl[r * vstride + (k0 >> 1) + w];
        }
        if (isY) {
            for (int idx = tid; idx < 2048; idx += 256) {
                int n = idx & 127, kk = idx >> 7;
                int gm = k0 + kk, gn = c0out + n;
                float v = (gm < MY && gn < NX) ? hb[gm * NX + gn] : 0.f;
                __nv_bfloat16 h16, l16; bsplit(v, h16, l16);
                sXh[n * 16 + kk] = h16; sXl[n * 16 + kk] = l16;
            }
        } else {
            for (int idx = tid; idx < 2048; idx += 256) {
                int kk = idx & 15, m = idx >> 4;
                int gm = c0out + m, gn = k0 + kk;
                float v = (gm < MY && gn < NX) ? hb[gm * NX + gn] : 0.f;
                __nv_bfloat16 h16, l16; bsplit(v, h16, l16);
                sXh[m * 16 + kk] = h16; sXl[m * 16 + kk] = l16;
            }
        }
        __syncthreads();

        int kp = (lane & 3) * 2;
        int rgrp = lane >> 2;
        unsigned ah[2][4], al[2][4];
#pragma unroll
        for (int rt = 0; rt < 2; rt++) {
            int r = wrow + rt * 16 + rgrp;
            ah[rt][0] = *(const unsigned*)&sVh[r * 16 + kp];
            ah[rt][1] = *(const unsigned*)&sVh[(r + 8) * 16 + kp];
            ah[rt][2] = *(const unsigned*)&sVh[r * 16 + kp + 8];
            ah[rt][3] = *(const unsigned*)&sVh[(r + 8) * 16 + kp + 8];
            al[rt][0] = *(const unsigned*)&sVl[r * 16 + kp];
            al[rt][1] = *(const unsigned*)&sVl[(r + 8) * 16 + kp];
            al[rt][2] = *(const unsigned*)&sVl[r * 16 + kp + 8];
            al[rt][3] = *(const unsigned*)&sVl[(r + 8) * 16 + kp + 8];
        }
        unsigned bh[4][2], bl[4][2];
#pragma unroll
        for (int c = 0; c < 4; c++) {
            int n = wcol + c * 8 + rgrp;
            bh[c][0] = *(const unsigned*)&sXh[n * 16 + kp];
            bh[c][1] = *(const unsigned*)&sXh[n * 16 + kp + 8];
            bl[c][0] = *(const unsigned*)&sXl[n * 16 + kp];
            bl[c][1] = *(const unsigned*)&sXl[n * 16 + kp + 8];
        }
#pragma unroll
        for (int rt = 0; rt < 2; rt++)
#pragma unroll
            for (int c = 0; c < 4; c++) {
                mma16816(d[rt][c], ah[rt], bh[c]);
                mma16816(d[rt][c], ah[rt], bl[c]);
                mma16816(d[rt][c], al[rt], bh[c]);
            }
        __syncthreads();
    }

    float* outr = isY ? g_ftyr : g_ftxr;
    float* outi = isY ? g_ftyi : g_ftxi;
#pragma unroll
    for (int rt = 0; rt < 2; rt++) {
        int r0 = wrow + rt * 16 + (lane >> 2);
#pragma unroll
        for (int c = 0; c < 4; c++) {
            int col = c0out + wcol + c * 8 + (lane & 3) * 2;
            if (col < Lout) {
                int k0m = r0 & 31;
                float* base0 = (r0 < 32 ? outr : outi);
                *(float2*)&base0[((size_t)bi * KM + k0m) * Lout + col] =
                    make_float2(d[rt][c][0], d[rt][c][1]);
                int r2 = r0 + 8;
                int k2m = r2 & 31;
                float* base2 = (r2 < 32 ? outr : outi);
                *(float2*)&base2[((size_t)bi * KM + k2m) * Lout + col] =
                    make_float2(d[rt][c][2], d[rt][c][3]);
            }
        }
    }
}

// ---------------- fused mode mix: writes bf16-split transposed outputs for invK ----------------
__global__ void __launch_bounds__(256) mixFK(const float* __restrict__ fw1,
                                             const float* __restrict__ fw2) {
    int isY = (blockIdx.x < 3);
    const float* fw = isY ? fw1 : fw2;
    const float* finr = isY ? g_ftyr : g_ftxr;
    const float* fini = isY ? g_ftyi : g_ftxi;
    __nv_bfloat16* tH = isY ? g_oyTh : g_oxTh;
    __nv_bfloat16* tL = isY ? g_oyTl : g_oxTl;
    int Lpad = isY ? 384 : 192;
    int L = isY ? NX : MY;
    int l0 = (isY ? blockIdx.x : (blockIdx.x - 3)) * 128;

    int b = blockIdx.z, k = blockIdx.y;
    int tid = threadIdx.x;
    int og = tid >> 5, lg = tid & 31;

    __shared__ float  sWr[32][32], sWi[32][32];
    __shared__ float4 sFr[32][32], sFi[32][32];

    for (int idx = tid; idx < 512; idx += 256) {
        int i = idx >> 5, l4 = idx & 31;
        int gl = l0 + l4 * 4;
        size_t off = ((size_t)(b * CW + i) * KM + k) * L + gl;
        int sz = (gl < L) ? 16 : 0;
        cpa16(&sFr[i][l4], &finr[off], sz);
        cpa16(&sFi[i][l4], &fini[off], sz);
    }
    CPA_COMMIT();
    for (int idx = 512 + tid; idx < 1024; idx += 256) {
        int i = idx >> 5, l4 = idx & 31;
        int gl = l0 + l4 * 4;
        size_t off = ((size_t)(b * CW + i) * KM + k) * L + gl;
        int sz = (gl < L) ? 16 : 0;
        cpa16(&sFr[i][l4], &finr[off], sz);
        cpa16(&sFi[i][l4], &fini[off], sz);
    }
    CPA_COMMIT();
    for (int idx = tid; idx < 1024; idx += 256) {
        int i = idx >> 5, o = idx & 31;
        const float* p = fw + ((size_t)(i * 32 + o) * KM + k) * 2;
        sWr[i][o] = p[0]; sWi[i][o] = p[1];
    }

    float cr[4][4], ci[4][4];
#pragma unroll
    for (int a = 0; a < 4; a++)
#pragma unroll
        for (int j = 0; j < 4; j++) { cr[a][j] = 0.f; ci[a][j] = 0.f; }

    CPA_WAIT1();
    __syncthreads();

#pragma unroll 4
    for (int i = 0; i < 16; i++) {
        float4 fr4 = sFr[i][lg], fi4 = sFi[i][lg];
        float fr[4] = {fr4.x, fr4.y, fr4.z, fr4.w};
        float fi[4] = {fi4.x, fi4.y, fi4.z, fi4.w};
        float4 wr4 = *(const float4*)&sWr[i][og * 4];
        float4 wi4 = *(const float4*)&sWi[i][og * 4];
        float wr[4] = {wr4.x, wr4.y, wr4.z, wr4.w};
        float wi[4] = {wi4.x, wi4.y, wi4.z, wi4.w};
#pragma unroll
        for (int a = 0; a < 4; a++) {
            float wrv = wr[a], wiv = wi[a];
#pragma unroll
            for (int j = 0; j < 4; j++) {
                cr[a][j] = fmaf(wrv, fr[j], cr[a][j]);
                cr[a][j] = fmaf(-wiv, fi[j], cr[a][j]);
                ci[a][j] = fmaf(wrv, fi[j], ci[a][j]);
                ci[a][j] = fmaf(wiv, fr[j], ci[a][j]);
            }
        }
    }

    CPA_WAIT0();
    __syncthreads();

#pragma unroll 4
    for (int i = 16; i < 32; i++) {
        float4 fr4 = sFr[i][lg], fi4 = sFi[i][lg];
        float fr[4] = {fr4.x, fr4.y, fr4.z, fr4.w};
        float fi[4] = {fi4.x, fi4.y, fi4.z, fi4.w};
        float4 wr4 = *(const float4*)&sWr[i][og * 4];
        float4 wi4 = *(const float4*)&sWi[i][og * 4];
        float wr[4] = {wr4.x, wr4.y, wr4.z, wr4.w};
        float wi[4] = {wi4.x, wi4.y, wi4.z, wi4.w};
#pragma unroll
        for (int a = 0; a < 4; a++) {
            float wrv = wr[a], wiv = wi[a];
#pragma unroll
            for (int j = 0; j < 4; j++) {
                cr[a][j] = fmaf(wrv, fr[j], cr[a][j]);
                cr[a][j] = fmaf(-wiv, fi[j], cr[a][j]);
                ci[a][j] = fmaf(wrv, fi[j], ci[a][j]);
                ci[a][j] = fmaf(wiv, fr[j], ci[a][j]);
            }
        }
    }

    // epilogue: scattered bf16-split stores in [bo][l][64] layout (k at col k, imag at k+32)
    int glb = l0 + lg * 4;
#pragma unroll
    for (int a = 0; a < 4; a++) {
        int o = og * 4 + a;
        size_t rowbase = ((size_t)(b * CW + o) * Lpad);
#pragma unroll
        for (int j = 0; j < 4; j++) {
            int l = glb + j;
            if (l < L) {
                size_t base = (rowbase + l) * 64 + k;
                __nv_bfloat16 h16, l16;
                bsplit(cr[a][j], h16, l16);
                tH[base] = h16; tL[base] = l16;
                bsplit(ci[a][j], h16, l16);
                tH[base + 32] = h16; tL[base + 32] = l16;
            }
        }
    }
}

// ---------------- tensor-core inverse: x1[m][n] = A[m][128] * B[128][n] ----------------
// A = [VyT_r | VyT_i | OxT_r | OxT_i], B = [OyT_r ; OyT_i ; VxT_r ; VxT_i]
__global__ void __launch_bounds__(256) invK() {
    int bo = blockIdx.z;
    int m0 = blockIdx.y * 64;
    int n0 = blockIdx.x * 128;
    int tid = threadIdx.x;
    int lane = tid & 31, wid = tid >> 5;
    int wrow = (wid & 1) * 32;
    int wcol = (wid >> 1) * 32;

    __shared__ __align__(16) char sBuf[12288];
    __nv_bfloat16* sAh = (__nv_bfloat16*)sBuf;            // [64][16]
    __nv_bfloat16* sAl = (__nv_bfloat16*)(sBuf + 2048);   // [64][16]
    __nv_bfloat16* sBh = (__nv_bfloat16*)(sBuf + 4096);   // [128][16]
    __nv_bfloat16* sBl = (__nv_bfloat16*)(sBuf + 8192);   // [128][16]

    float d[2][4][4];
#pragma unroll
    for (int rt = 0; rt < 2; rt++)
#pragma unroll
        for (int c = 0; c < 4; c++)
#pragma unroll
            for (int j = 0; j < 4; j++) d[rt][c][j] = 0.f;

    for (int kc = 0; kc < 8; kc++) {
        int k0 = kc * 16;
        // A rows: 64 rows x (h,l): 128 tasks
        if (tid < 128) {
            int r = tid & 63, which = tid >> 6;
            int gm = m0 + r;
            const __nv_bfloat16* src;
            if (k0 < 64)
                src = (which ? g_VyTl : g_VyTh) + gm * 64 + k0;
            else
                src = (which ? g_oxTl : g_oxTh) + ((size_t)bo * 192 + gm) * 64 + (k0 - 64);
            __nv_bfloat16* dst = (which ? sAl : sAh) + r * 16;
            cpa16(dst, src, 16);
            cpa16(dst + 8, src + 8, 16);
        } else {
            // B rows: 128 rows x (h,l): 256 tasks, 128 threads x 2
            int t2 = tid - 128;
#pragma unroll
            for (int q = 0; q < 2; q++) {
                int task = t2 * 2 + q;
                int r = task & 127, which = task >> 7;
                int gn = n0 + r;
                const __nv_bfloat16* src;
                if (k0 < 64)
                    src = (which ? g_oyTl : g_oyTh) + ((size_t)bo * 384 + gn) * 64 + k0;
                else
                    src = (which ? g_VxTl : g_VxTh) + gn * 64 + (k0 - 64);
                __nv_bfloat16* dst = (which ? sBl : sBh) + r * 16;
                cpa16(dst, src, 16);
                cpa16(dst + 8, src + 8, 16);
            }
        }
        CPA_COMMIT();
        CPA_WAIT0();
        __syncthreads();

        int kp = (lane & 3) * 2;
        int rgrp = lane >> 2;
        unsigned ah[2][4], al[2][4];
#pragma unroll
        for (int rt = 0; rt < 2; rt++) {
            int r = wrow + rt * 16 + rgrp;
            ah[rt][0] = *(const unsigned*)&sAh[r * 16 + kp];
            ah[rt][1] = *(const unsigned*)&sAh[(r + 8) * 16 + kp];
            ah[rt][2] = *(const unsigned*)&sAh[r * 16 + kp + 8];
            ah[rt][3] = *(const unsigned*)&sAh[(r + 8) * 16 + kp + 8];
            al[rt][0] = *(const unsigned*)&sAl[r * 16 + kp];
            al[rt][1] = *(const unsigned*)&sAl[(r + 8) * 16 + kp];
            al[rt][2] = *(const unsigned*)&sAl[r * 16 + kp + 8];
            al[rt][3] = *(const unsigned*)&sAl[(r + 8) * 16 + kp + 8];
        }
        unsigned bh[4][2], bl[4][2];
#pragma unroll
        for (int c = 0; c < 4; c++) {
            int n = wcol + c * 8 + rgrp;
            bh[c][0] = *(const unsigned*)&sBh[n * 16 + kp];
            bh[c][1] = *(const unsigned*)&sBh[n * 16 + kp + 8];
            bl[c][0] = *(const unsigned*)&sBl[n * 16 + kp];
            bl[c][1] = *(const unsigned*)&sBl[n * 16 + kp + 8];
        }
#pragma unroll
        for (int rt = 0; rt < 2; rt++)
#pragma unroll
            for (int c = 0; c < 4; c++) {
                mma16816(d[rt][c], ah[rt], bh[c]);
                mma16816(d[rt][c], ah[rt], bl[c]);
                mma16816(d[rt][c], al[rt], bh[c]);
            }
        __syncthreads();
    }

    float* xb = g_x1 + (size_t)bo * PLANE;
#pragma unroll
    for (int rt = 0; rt < 2; rt++) {
        int r0 = wrow + rt * 16 + (lane >> 2);
        int m = m0 + r0;
#pragma unroll
        for (int c = 0; c < 4; c++) {
            int col = n0 + wcol + c * 8 + (lane & 3) * 2;
            if (col < NX) {
                if (m < MY)
                    *(float2*)&xb[m * NX + col] = make_float2(d[rt][c][0], d[rt][c][1]);
                int m2 = m + 8;
                if (m2 < MY)
                    *(float2*)&xb[m2 * NX + col] = make_float2(d[rt][c][2], d[rt][c][3]);
            }
        }
    }
}

// ---------------- pointwise MLP + residual ----------------
__global__ void __launch_bounds__(256) pwK(const float* __restrict__ w1, const float* __restrict__ b1,
                    const float* __restrict__ w2, const float* __restrict__ b2,
                    int applyGelu) {
    __shared__ float sX[32][128];
    __shared__ float sT[32][132];
    __shared__ float sW1[32][32], sW2[32][32];
    __shared__ float sB1[32], sB2[32];
    int tid = threadIdx.x;
    for (int idx = tid; idx < 1024; idx += 256) {
        int o = idx >> 5, c = idx & 31;
        sW1[c][o] = w1[o * 32 + c];
        sW2[c][o] = w2[o * 32 + c];
    }
    if (tid < 32) { sB1[tid] = b1[tid]; sB2[tid] = b2[tid]; }

    int p0 = blockIdx.x * 128;
    {
        int pp = tid & 127, ch = (tid >> 7) * 16;
        int p = p0 + pp;
        int b = p / PLANE, mn = p % PLANE;
        const float* src = g_x1 + ((size_t)b * CW + ch) * PLANE + mn;
#pragma unroll
        for (int cc = 0; cc < 16; cc++) sX[ch + cc][pp] = src[(size_t)cc * PLANE];
    }
    __syncthreads();

    int og = tid >> 5, pg = tid & 31;
    {
        float t[4][4];
#pragma unroll
        for (int a = 0; a < 4; a++) {
            float bb = sB1[og * 4 + a];
#pragma unroll
            for (int j = 0; j < 4; j++) t[a][j] = bb;
        }
#pragma unroll 4
        for (int c = 0; c < 32; c++) {
            float4 x4 = *(const float4*)&sX[c][pg * 4];
            float xv[4] = {x4.x, x4.y, x4.z, x4.w};
            float4 w4 = *(const float4*)&sW1[c][og * 4];
            float wv[4] = {w4.x, w4.y, w4.z, w4.w};
#pragma unroll
            for (int a = 0; a < 4; a++)
#pragma unroll
                for (int j = 0; j < 4; j++) t[a][j] = fmaf(wv[a], xv[j], t[a][j]);
        }
#pragma unroll
        for (int a = 0; a < 4; a++)
            *(float4*)&sT[og * 4 + a][pg * 4] =
                make_float4(geluf(t[a][0]), geluf(t[a][1]), geluf(t[a][2]), geluf(t[a][3]));
    }
    __syncthreads();
    {
        float t[4][4];
#pragma unroll
        for (int a = 0; a < 4; a++) {
            float bb = sB2[og * 4 + a];
#pragma unroll
            for (int j = 0; j < 4; j++) t[a][j] = bb;
        }
#pragma unroll 4
        for (int c = 0; c < 32; c++) {
            float4 x4 = *(const float4*)&sT[c][pg * 4];
            float xv[4] = {x4.x, x4.y, x4.z, x4.w};
            float4 w4 = *(const float4*)&sW2[c][og * 4];
            float wv[4] = {w4.x, w4.y, w4.z, w4.w};
#pragma unroll
            for (int a = 0; a < 4; a++)
#pragma unroll
                for (int j = 0; j < 4; j++) t[a][j] = fmaf(wv[a], xv[j], t[a][j]);
        }
        int pbase = p0 + pg * 4;
#pragma unroll
        for (int a = 0; a < 4; a++) {
            int o = og * 4 + a;
#pragma unroll
            for (int j = 0; j < 4; j++) {
                int p = pbase + j;
                int b = p / PLANE, mn = p % PLANE;
                size_t off = ((size_t)b * CW + o) * PLANE + mn;
                float s = t[a][j];
                if (applyGelu) s = geluf(s);
                g_h[off] += s;
            }
        }
    }
}

// ---------------- final head ----------------
__global__ void __launch_bounds__(256) finalK(const float* __restrict__ fc1w, const float* __restrict__ fc1b,
                       const float* __restrict__ fc2w, const float* __restrict__ fc2b,
                       float* __restrict__ out) {
    __shared__ float sX[32][68];
    __shared__ float sW1h[32][64];
    __shared__ float sT[64][68];
    __shared__ float sw2[128], sb1[128];
    __shared__ float sRed[4][64];
    int tid = threadIdx.x;
    if (tid < 128) { sw2[tid] = fc2w[tid]; sb1[tid] = fc1b[tid]; }

    int p0 = blockIdx.x * 64;
    {
        int pp = tid & 63, ch = (tid >> 6) * 8;
        int p = p0 + pp;
        int b = p / PLANE, mn = p % PLANE;
        const float* src = g_h + ((size_t)b * CW + ch) * PLANE + mn;
#pragma unroll
        for (int cc = 0; cc < 8; cc++) sX[ch + cc][pp] = src[(size_t)cc * PLANE];
    }

    float part = 0.f;
    for (int jh = 0; jh < 128; jh += 64) {
        __syncthreads();
        for (int idx = tid; idx < 512; idx += 256) {
            int c = idx >> 4, j4 = idx & 15;
            *(float4*)&sW1h[c][j4 * 4] = *(const float4*)&fc1w[c * 128 + jh + j4 * 4];
        }
        __syncthreads();

        int jg = tid >> 4, pgr = tid & 15;
        float t[4][4];
#pragma unroll
        for (int a = 0; a < 4; a++) {
            float bb = sb1[jh + jg * 4 + a];
#pragma unroll
            for (int j = 0; j < 4; j++) t[a][j] = bb;
        }
#pragma unroll 4
        for (int c = 0; c < 32; c++) {
            float4 x4 = *(const float4*)&sX[c][pgr * 4];
            float xv[4] = {x4.x, x4.y, x4.z, x4.w};
            float4 w4 = *(const float4*)&sW1h[c][jg * 4];
            float wv[4] = {w4.x, w4.y, w4.z, w4.w};
#pragma unroll
            for (int a = 0; a < 4; a++)
#pragma unroll
                for (int j = 0; j < 4; j++) t[a][j] = fmaf(wv[a], xv[j], t[a][j]);
        }
#pragma unroll
        for (int a = 0; a < 4; a++)
            *(float4*)&sT[jg * 4 + a][pgr * 4] =
                make_float4(geluf(t[a][0]), geluf(t[a][1]), geluf(t[a][2]), geluf(t[a][3]));
        __syncthreads();
        {
            int pq = tid & 63, jq = tid >> 6;
            float s = 0.f;
#pragma unroll
            for (int jj = 0; jj < 16; jj++) {
                int j = jq * 16 + jj;
                s = fmaf(sw2[jh + j], sT[j][pq], s);
            }
            part += s;
        }
    }
    __syncthreads();
    {
        int pq = tid & 63, jq = tid >> 6;
        sRed[jq][pq] = part;
    }
    __syncthreads();
    if (tid < 64) {
        out[p0 + tid] = sRed[0][tid] + sRed[1][tid] + sRed[2][tid] + sRed[3][tid] + fc2b[0];
    }
}

// ---------------- launch ----------------
extern "C" void kernel_launch(void* const* d_in, const int* in_sizes, int n_in,
                              void* d_out, int out_size) {
    (void)in_sizes; (void)n_in; (void)out_size;
    const float* x    = (const float*)d_in[0];
    const float* sx   = (const float*)d_in[1];
    const float* sy   = (const float*)d_in[2];
    const float* fc0w = (const float*)d_in[3];
    const float* fc0b = (const float*)d_in[4];
    const float* fw1  = (const float*)d_in[5];
    const float* fw2  = (const float*)d_in[6];
    const float* w1   = (const float*)d_in[7];
    const float* b1   = (const float*)d_in[8];
    const float* w2   = (const float*)d_in[9];
    const float* b2   = (const float*)d_in[10];
    const float* fc1w = (const float*)d_in[11];
    const float* fc1b = (const float*)d_in[12];
    const float* fc2w = (const float*)d_in[13];
    const float* fc2b = (const float*)d_in[14];
    float* out = (float*)d_out;

    precomputeK<<<128, 256>>>(sx, sy);
    fc0K<<<PIX / 128, 256>>>(x, fc0w, fc0b);

    for (int blk = 0; blk < 4; blk++) {
        const float* fw1p = fw1 + (size_t)blk * CW * CW * KM * 2;
        const float* fw2p = fw2 + (size_t)blk * CW * CW * KM * 2;
        const float* w1p  = w1 + (size_t)blk * CW * CW;
        const float* b1p  = b1 + (size_t)blk * CW;
        const float* w2p  = w2 + (size_t)blk * CW * CW;
        const float* b2p  = b2 + (size_t)blk * CW;

        ftK<<<dim3(5, BSZ * CW), 256>>>();
        mixFK<<<dim3(5, KM, BSZ), 256>>>(fw1p, fw2p);
        invK<<<dim3(3, 3, BSZ * CW), 256>>>();
        pwK<<<PIX / 128, 256>>>(w1p, b1p, w2p, b2p, blk < 3 ? 1 : 0);
    }

    finalK<<<PIX / 64, 256>>>(fc1w, fc1b, fc2w, fc2b, out);
}

// round 14
// speedup vs baseline: 1.3223x; 1.3223x over previous
#include <cuda_runtime.h>
#include <cuda_bf16.h>
#include <math.h>

#define BSZ 16
#define CW  32
#define MY  180
#define NX  360
#define KM  32
#define PLANE (MY*NX)
#define PIX (BSZ*PLANE)

__device__ __forceinline__ float geluf(float x) {
    return 0.5f * x * (1.0f + erff(x * 0.70710678118654752f));
}

__device__ __forceinline__ void cpa16(void* dst, const void* src, int szbytes) {
    unsigned d = (unsigned)__cvta_generic_to_shared(dst);
    asm volatile("cp.async.cg.shared.global [%0], [%1], 16, %2;"
                 :: "r"(d), "l"(src), "r"(szbytes) : "memory");
}
#define CPA_COMMIT() asm volatile("cp.async.commit_group;" ::: "memory")
#define CPA_WAIT0()  asm volatile("cp.async.wait_group 0;" ::: "memory")
#define CPA_WAIT1()  asm volatile("cp.async.wait_group 1;" ::: "memory")

// m16n8k16 bf16 MMA, fp32 accum
__device__ __forceinline__ void mma16816(float* d, const unsigned* a, const unsigned* b) {
    asm volatile(
        "mma.sync.aligned.m16n8k16.row.col.f32.bf16.bf16.f32 "
        "{%0,%1,%2,%3},{%4,%5,%6,%7},{%8,%9},{%0,%1,%2,%3};"
        : "+f"(d[0]), "+f"(d[1]), "+f"(d[2]), "+f"(d[3])
        : "r"(a[0]), "r"(a[1]), "r"(a[2]), "r"(a[3]), "r"(b[0]), "r"(b[1]));
}

__device__ __forceinline__ void bsplit(float v, __nv_bfloat16& h, __nv_bfloat16& l) {
    h = __float2bfloat16(v);
    l = __float2bfloat16(v - __bfloat162float(h));
}

// ---------------- device scratch ----------------
__device__ __align__(16) float g_h  [BSZ*CW*PLANE];
__device__ __align__(16) float g_x1 [BSZ*CW*PLANE];
__device__ __align__(16) float g_ftyr[BSZ*CW*KM*NX];
__device__ __align__(16) float g_ftyi[BSZ*CW*KM*NX];
__device__ __align__(16) float g_oyr [BSZ*CW*KM*NX];
__device__ __align__(16) float g_oyi [BSZ*CW*KM*NX];
__device__ __align__(16) float g_ftxr[BSZ*CW*KM*MY];
__device__ __align__(16) float g_ftxi[BSZ*CW*KM*MY];
__device__ __align__(16) float g_oxr [BSZ*CW*KM*MY];
__device__ __align__(16) float g_oxi [BSZ*CW*KM*MY];
__device__ __align__(16) float g_Vyr [KM*MY], g_Vyi [KM*MY];   // [k][m]
__device__ __align__(16) float g_Vxr [KM*NX], g_Vxi [KM*NX];   // [k][n]
// bf16-split stacked V matrices for forward transforms (rows 0..31 real, 32..63 imag)
#define KPY 192
#define KPX 384
__device__ __align__(16) __nv_bfloat16 g_Vych[64*KPY], g_Vycl[64*KPY];
__device__ __align__(16) __nv_bfloat16 g_Vxch[64*KPX], g_Vxcl[64*KPX];
__device__ float g_gx[NX], g_gy[MY];

// ---------------- precompute ----------------
__global__ void precomputeK(const float* __restrict__ sx,
                            const float* __restrict__ sy) {
    int t = blockIdx.x * blockDim.x + threadIdx.x;
    int stride = gridDim.x * blockDim.x;
    float x0 = sx[0], xL = sx[NX - 1];
    float y0 = sy[0], yL = sy[MY - 1];
    float invRX = 1.0f / (xL - x0), invRY = 1.0f / (yL - y0);
    float invSqN = rsqrtf((float)NX), invSqM = rsqrtf((float)MY);
    const float TWO_PI = 6.283185307179586f;
    __nv_bfloat16 z16 = __float2bfloat16(0.f);

    for (int idx = t; idx < 64 * (KPY - MY); idx += stride) {
        int r = idx / (KPY - MY), m = MY + idx % (KPY - MY);
        g_Vych[r * KPY + m] = z16; g_Vycl[r * KPY + m] = z16;
    }
    for (int idx = t; idx < 64 * (KPX - NX); idx += stride) {
        int r = idx / (KPX - NX), n = NX + idx % (KPX - NX);
        g_Vxch[r * KPX + n] = z16; g_Vxcl[r * KPX + n] = z16;
    }

    for (int idx = t; idx < KM * NX; idx += stride) {
        int k = idx / NX, n = idx % NX;
        float p = (sx[n] - x0) * invRX;
        float s, c; sincosf(-TWO_PI * (float)k * p, &s, &c);
        float vr = c * invSqN, vi = s * invSqN;
        g_Vxr[idx] = vr; g_Vxi[idx] = vi;
        __nv_bfloat16 h16, l16;
        bsplit(vr, h16, l16);
        g_Vxch[k * KPX + n] = h16; g_Vxcl[k * KPX + n] = l16;
        bsplit(vi, h16, l16);
        g_Vxch[(k + 32) * KPX + n] = h16; g_Vxcl[(k + 32) * KPX + n] = l16;
    }
    for (int idx = t; idx < KM * MY; idx += stride) {
        int k = idx / MY, m = idx % MY;
        float p = (sy[m] - y0) * invRY;
        float s, c; sincosf(-TWO_PI * (float)k * p, &s, &c);
        float vr = c * invSqM, vi = s * invSqM;
        g_Vyr[idx] = vr; g_Vyi[idx] = vi;
        __nv_bfloat16 h16, l16;
        bsplit(vr, h16, l16);
        g_Vych[k * KPY + m] = h16; g_Vycl[k * KPY + m] = l16;
        bsplit(vi, h16, l16);
        g_Vych[(k + 32) * KPY + m] = h16; g_Vycl[(k + 32) * KPY + m] = l16;
    }
    for (int n = t; n < NX; n += stride) g_gx[n] = (sx[n] - x0) / xL;
    for (int m = t; m < MY; m += stride) g_gy[m] = (sy[m] - y0) / yL;
}

// ---------------- fc0 ----------------
__global__ void fc0K(const float* __restrict__ x,
                     const float* __restrict__ w,
                     const float* __restrict__ bias) {
    __shared__ float sX[18][128];
    __shared__ float sW[18][32];
    __shared__ float sB[32];
    int tid = threadIdx.x;
    for (int idx = tid; idx < 18 * 32; idx += 256) sW[idx >> 5][idx & 31] = w[idx];
    if (tid < 32) sB[tid] = bias[tid];

    int p0 = blockIdx.x * 128;
    {
        int pp = tid & 127, hf = tid >> 7;
        int p = p0 + pp;
        const float4* xp = (const float4*)(x + (size_t)p * 16) + hf * 2;
        float4 a = xp[0], b4 = xp[1];
        int c0 = hf * 8;
        sX[c0 + 0][pp] = a.x;  sX[c0 + 1][pp] = a.y;
        sX[c0 + 2][pp] = a.z;  sX[c0 + 3][pp] = a.w;
        sX[c0 + 4][pp] = b4.x; sX[c0 + 5][pp] = b4.y;
        sX[c0 + 6][pp] = b4.z; sX[c0 + 7][pp] = b4.w;
        if (hf == 0) {
            int mn = p % PLANE;
            sX[16][pp] = g_gx[mn % NX];
            sX[17][pp] = g_gy[mn / NX];
        }
    }
    __syncthreads();

    int og = tid >> 5, pg = tid & 31;
    float t[4][4];
#pragma unroll
    for (int a = 0; a < 4; a++) {
        float bb = sB[og * 4 + a];
#pragma unroll
        for (int j = 0; j < 4; j++) t[a][j] = bb;
    }

#pragma unroll 2
    for (int c = 0; c < 18; c++) {
        float4 x4 = *(const float4*)&sX[c][pg * 4];
        float xv[4] = {x4.x, x4.y, x4.z, x4.w};
        float4 w4 = *(const float4*)&sW[c][og * 4];
        float wv[4] = {w4.x, w4.y, w4.z, w4.w};
#pragma unroll
        for (int a = 0; a < 4; a++)
#pragma unroll
            for (int j = 0; j < 4; j++) t[a][j] = fmaf(wv[a], xv[j], t[a][j]);
    }
#pragma unroll
    for (int a = 0; a < 4; a++) {
        int o = og * 4 + a;
#pragma unroll
        for (int j = 0; j < 4; j++) {
            int p = p0 + pg * 4 + j;
            int b = p / PLANE, mn = p % PLANE;
            g_h[((size_t)b * CW + o) * PLANE + mn] = t[a][j];
        }
    }
}

// ---------------- tensor-core forward transforms, cp.async double-buffered staging ----------------
// C[64 stacked modes][128 cols] = Vcat[64 x Kpad] * X[Kpad x 128], bf16 hi/lo split.
__global__ void __launch_bounds__(256) ftK() {
    int bi = blockIdx.y;
    int tid = threadIdx.x;
    int lane = tid & 31, wid = tid >> 5;
    int wrow = (wid & 1) * 32;
    int wcol = (wid >> 1) * 32;
    const float* hb = g_h + (size_t)bi * PLANE;

    // smem: fp32 tile 2x8KB, Vh/Vl 2x2KB each, Xh/Xl 4KB each = 32KB
    __shared__ __align__(16) float        sF32[2][2048];       // 16KB
    __shared__ __align__(16) __nv_bfloat16 sVh[2][1024];       // 4KB
    __shared__ __align__(16) __nv_bfloat16 sVl[2][1024];       // 4KB
    __shared__ __align__(16) __nv_bfloat16 sXh[2048];          // 4KB  [col][16]
    __shared__ __align__(16) __nv_bfloat16 sXl[2048];          // 4KB

    int isY = (blockIdx.x < 3);
    int c0out = isY ? blockIdx.x * 128 : (blockIdx.x - 3) * 128;
    int nChunks = isY ? (KPY / 16) : (KPX / 16);
    int Kreal = isY ? MY : NX;
    int Lout = isY ? NX : MY;
    const unsigned* gVh = (const unsigned*)(isY ? g_Vych : g_Vxch);
    const unsigned* gVl = (const unsigned*)(isY ? g_Vycl : g_Vxcl);
    int vstride = (isY ? KPY : KPX) >> 1;   // row stride in u32

    float d[2][4][4];
#pragma unroll
    for (int rt = 0; rt < 2; rt++)
#pragma unroll
        for (int c = 0; c < 4; c++)
#pragma unroll
            for (int j = 0; j < 4; j++) d[rt][c][j] = 0.f;

    // ---- staging helper (inlined twice): stage chunk kc into buffer kc&1 ----
    // fp32 tile layout: fty: [kk(16)][n(128)] ; ftx: [m(128)][kk(16)]
#define STAGE_CHUNK(KC)                                                          \
    {                                                                            \
        int k0s = (KC) * 16;                                                     \
        int bufs = (KC) & 1;                                                     \
        if (isY) {                                                               \
            /* 16 rows x 32 granules(16B) = 512 tasks */                         \
            for (int idx = tid; idx < 512; idx += 256) {                         \
                int kk = idx >> 5, g = idx & 31;                                 \
                int gm = k0s + kk, gn = c0out + g * 4;                           \
                int sz = (gm < Kreal && gn < NX) ? 16 : 0;                       \
                cpa16(&sF32[bufs][kk * 128 + g * 4], &hb[gm * NX + gn], sz);     \
            }                                                                    \
        } else {                                                                 \
            /* 128 rows x 4 granules = 512 tasks */                              \
            for (int idx = tid; idx < 512; idx += 256) {                         \
                int m = idx >> 2, g = idx & 3;                                   \
                int gm = c0out + m, gn = k0s + g * 4;                            \
                int sz = (gm < MY && gn < Kreal) ? 16 : 0;                       \
                cpa16(&sF32[bufs][m * 16 + g * 4], &hb[gm * NX + gn], sz);       \
            }                                                                    \
        }                                                                        \
        /* V slice: 64 rows x 2 granules (32B) per array = 128 tasks each */     \
        for (int idx = tid; idx < 256; idx += 256) { }                           \
        for (int idx = tid; idx < 128; idx += 256) {                             \
            int r = idx >> 1, g = idx & 1;                                       \
            cpa16(&sVh[bufs][r * 16 + g * 8], &gVh[r * vstride + (k0s >> 1) + g * 4], 16); \
            cpa16(&sVl[bufs][r * 16 + g * 8], &gVl[r * vstride + (k0s >> 1) + g * 4], 16); \
        }                                                                        \
        CPA_COMMIT();                                                            \
    }

    STAGE_CHUNK(0)

    for (int kc = 0; kc < nChunks; kc++) {
        if (kc + 1 < nChunks) {
            STAGE_CHUNK(kc + 1)
            CPA_WAIT1();
        } else {
            CPA_WAIT0();
        }
        __syncthreads();

        int cur = kc & 1;
        // convert fp32 tile -> split bf16 [col][16]
        if (isY) {
            for (int idx = tid; idx < 2048; idx += 256) {
                int n = idx & 127, kk = idx >> 7;
                float v = sF32[cur][kk * 128 + n];
                __nv_bfloat16 h16, l16; bsplit(v, h16, l16);
                sXh[n * 16 + kk] = h16; sXl[n * 16 + kk] = l16;
            }
        } else {
            for (int idx = tid; idx < 2048; idx += 256) {
                int kk = idx & 15, m = idx >> 4;
                float v = sF32[cur][m * 16 + kk];
                __nv_bfloat16 h16, l16; bsplit(v, h16, l16);
                sXh[m * 16 + kk] = h16; sXl[m * 16 + kk] = l16;
            }
        }
        __syncthreads();

        int kp = (lane & 3) * 2;
        int rgrp = lane >> 2;
        unsigned ah[2][4], al[2][4];
#pragma unroll
        for (int rt = 0; rt < 2; rt++) {
            int r = wrow + rt * 16 + rgrp;
            ah[rt][0] = *(const unsigned*)&sVh[cur][r * 16 + kp];
            ah[rt][1] = *(const unsigned*)&sVh[cur][(r + 8) * 16 + kp];
            ah[rt][2] = *(const unsigned*)&sVh[cur][r * 16 + kp + 8];
            ah[rt][3] = *(const unsigned*)&sVh[cur][(r + 8) * 16 + kp + 8];
            al[rt][0] = *(const unsigned*)&sVl[cur][r * 16 + kp];
            al[rt][1] = *(const unsigned*)&sVl[cur][(r + 8) * 16 + kp];
            al[rt][2] = *(const unsigned*)&sVl[cur][r * 16 + kp + 8];
            al[rt][3] = *(const unsigned*)&sVl[cur][(r + 8) * 16 + kp + 8];
        }
        unsigned bh[4][2], bl[4][2];
#pragma unroll
        for (int c = 0; c < 4; c++) {
            int n = wcol + c * 8 + rgrp;
            bh[c][0] = *(const unsigned*)&sXh[n * 16 + kp];
            bh[c][1] = *(const unsigned*)&sXh[n * 16 + kp + 8];
            bl[c][0] = *(const unsigned*)&sXl[n * 16 + kp];
            bl[c][1] = *(const unsigned*)&sXl[n * 16 + kp + 8];
        }
#pragma unroll
        for (int rt = 0; rt < 2; rt++)
#pragma unroll
            for (int c = 0; c < 4; c++) {
                mma16816(d[rt][c], ah[rt], bh[c]);
                mma16816(d[rt][c], ah[rt], bl[c]);
                mma16816(d[rt][c], al[rt], bh[c]);
            }
        __syncthreads();
    }
#undef STAGE_CHUNK

    float* outr = isY ? g_ftyr : g_ftxr;
    float* outi = isY ? g_ftyi : g_ftxi;
#pragma unroll
    for (int rt = 0; rt < 2; rt++) {
        int r0 = wrow + rt * 16 + (lane >> 2);
#pragma unroll
        for (int c = 0; c < 4; c++) {
            int col = c0out + wcol + c * 8 + (lane & 3) * 2;
            if (col < Lout) {
                int k0m = r0 & 31;
                float* base0 = (r0 < 32 ? outr : outi);
                *(float2*)&base0[((size_t)bi * KM + k0m) * Lout + col] =
                    make_float2(d[rt][c][0], d[rt][c][1]);
                int r2 = r0 + 8;
                int k2m = r2 & 31;
                float* base2 = (r2 < 32 ? outr : outi);
                *(float2*)&base2[((size_t)bi * KM + k2m) * Lout + col] =
                    make_float2(d[rt][c][2], d[rt][c][3]);
            }
        }
    }
}

// ---------------- fused mode mix (R8/R12 version, fp32 outputs) ----------------
__global__ void __launch_bounds__(256) mixFK(const float* __restrict__ fw1,
                                             const float* __restrict__ fw2) {
    int isY = (blockIdx.x < 3);
    const float* fw = isY ? fw1 : fw2;
    const float* finr = isY ? g_ftyr : g_ftxr;
    const float* fini = isY ? g_ftyi : g_ftxi;
    float* foutr = isY ? g_oyr : g_oxr;
    float* fouti = isY ? g_oyi : g_oxi;
    int L = isY ? NX : MY;
    int l0 = (isY ? blockIdx.x : (blockIdx.x - 3)) * 128;

    int b = blockIdx.z, k = blockIdx.y;
    int tid = threadIdx.x;
    int og = tid >> 5, lg = tid & 31;

    __shared__ float  sWr[32][32], sWi[32][32];
    __shared__ float4 sFr[32][32], sFi[32][32];

    for (int idx = tid; idx < 512; idx += 256) {
        int i = idx >> 5, l4 = idx & 31;
        int gl = l0 + l4 * 4;
        size_t off = ((size_t)(b * CW + i) * KM + k) * L + gl;
        int sz = (gl < L) ? 16 : 0;
        cpa16(&sFr[i][l4], &finr[off], sz);
        cpa16(&sFi[i][l4], &fini[off], sz);
    }
    CPA_COMMIT();
    for (int idx = 512 + tid; idx < 1024; idx += 256) {
        int i = idx >> 5, l4 = idx & 31;
        int gl = l0 + l4 * 4;
        size_t off = ((size_t)(b * CW + i) * KM + k) * L + gl;
        int sz = (gl < L) ? 16 : 0;
        cpa16(&sFr[i][l4], &finr[off], sz);
        cpa16(&sFi[i][l4], &fini[off], sz);
    }
    CPA_COMMIT();
    for (int idx = tid; idx < 1024; idx += 256) {
        int i = idx >> 5, o = idx & 31;
        const float* p = fw + ((size_t)(i * 32 + o) * KM + k) * 2;
        sWr[i][o] = p[0]; sWi[i][o] = p[1];
    }

    float cr[4][4], ci[4][4];
#pragma unroll
    for (int a = 0; a < 4; a++)
#pragma unroll
        for (int j = 0; j < 4; j++) { cr[a][j] = 0.f; ci[a][j] = 0.f; }

    CPA_WAIT1();
    __syncthreads();

#pragma unroll 4
    for (int i = 0; i < 16; i++) {
        float4 fr4 = sFr[i][lg], fi4 = sFi[i][lg];
        float fr[4] = {fr4.x, fr4.y, fr4.z, fr4.w};
        float fi[4] = {fi4.x, fi4.y, fi4.z, fi4.w};
        float4 wr4 = *(const float4*)&sWr[i][og * 4];
        float4 wi4 = *(const float4*)&sWi[i][og * 4];
        float wr[4] = {wr4.x, wr4.y, wr4.z, wr4.w};
        float wi[4] = {wi4.x, wi4.y, wi4.z, wi4.w};
#pragma unroll
        for (int a = 0; a < 4; a++) {
            float wrv = wr[a], wiv = wi[a];
#pragma unroll
            for (int j = 0; j < 4; j++) {
                cr[a][j] = fmaf(wrv, fr[j], cr[a][j]);
                cr[a][j] = fmaf(-wiv, fi[j], cr[a][j]);
                ci[a][j] = fmaf(wrv, fi[j], ci[a][j]);
                ci[a][j] = fmaf(wiv, fr[j], ci[a][j]);
            }
        }
    }

    CPA_WAIT0();
    __syncthreads();

#pragma unroll 4
    for (int i = 16; i < 32; i++) {
        float4 fr4 = sFr[i][lg], fi4 = sFi[i][lg];
        float fr[4] = {fr4.x, fr4.y, fr4.z, fr4.w};
        float fi[4] = {fi4.x, fi4.y, fi4.z, fi4.w};
        float4 wr4 = *(const float4*)&sWr[i][og * 4];
        float4 wi4 = *(const float4*)&sWi[i][og * 4];
        float wr[4] = {wr4.x, wr4.y, wr4.z, wr4.w};
        float wi[4] = {wi4.x, wi4.y, wi4.z, wi4.w};
#pragma unroll
        for (int a = 0; a < 4; a++) {
            float wrv = wr[a], wiv = wi[a];
#pragma unroll
            for (int j = 0; j < 4; j++) {
                cr[a][j] = fmaf(wrv, fr[j], cr[a][j]);
                cr[a][j] = fmaf(-wiv, fi[j], cr[a][j]);
                ci[a][j] = fmaf(wrv, fi[j], ci[a][j]);
                ci[a][j] = fmaf(wiv, fr[j], ci[a][j]);
            }
        }
    }

    int gl = l0 + lg * 4;
    if (gl < L) {
#pragma unroll
        for (int a = 0; a < 4; a++) {
            int o = og * 4 + a;
            size_t off = ((size_t)(b * CW + o) * KM + k) * L + gl;
            *(float4*)&foutr[off] = make_float4(cr[a][0], cr[a][1], cr[a][2], cr[a][3]);
            *(float4*)&fouti[off] = make_float4(ci[a][0], ci[a][1], ci[a][2], ci[a][3]);
        }
    }
}

// ---------------- fused inverse (R8/R12 scalar version) ----------------
__global__ void __launch_bounds__(256) invK() {
    int bo = blockIdx.z;
    int m0 = blockIdx.y * 64;
    int n0 = blockIdx.x * 64;
    int tid = threadIdx.x;
    int mg = tid >> 4, ng = tid & 15;
    int mlim = (m0 == 128) ? 13 : 16;
    int nlim = (n0 == 320) ? 10 : 16;

    __shared__ float4 sVyr[2][8][16], sVyi[2][8][16], sOxr[2][8][16], sOxi[2][8][16];
    __shared__ float4 sOyr[2][8][16], sOyi[2][8][16], sVxr[2][8][16], sVxi[2][8][16];

    float acc[4][4];
#pragma unroll
    for (int a = 0; a < 4; a++)
#pragma unroll
        for (int j = 0; j < 4; j++) acc[a][j] = 0.f;

    if (tid < 128) {
        int kk = tid >> 4, q = tid & 15;
        int kabs = kk;
        int msz = (q < mlim) ? 16 : 0;
        int nsz = (q < nlim) ? 16 : 0;
        size_t obY = ((size_t)bo * KM + kabs) * NX + n0 + q * 4;
        size_t obX = ((size_t)bo * KM + kabs) * MY + m0 + q * 4;
        cpa16(&sVyr[0][kk][q], &g_Vyr[kabs * MY + m0 + q * 4], msz);
        cpa16(&sVyi[0][kk][q], &g_Vyi[kabs * MY + m0 + q * 4], msz);
        cpa16(&sOxr[0][kk][q], &g_oxr[obX], msz);
        cpa16(&sOxi[0][kk][q], &g_oxi[obX], msz);
        cpa16(&sOyr[0][kk][q], &g_oyr[obY], nsz);
        cpa16(&sOyi[0][kk][q], &g_oyi[obY], nsz);
        cpa16(&sVxr[0][kk][q], &g_Vxr[kabs * NX + n0 + q * 4], nsz);
        cpa16(&sVxi[0][kk][q], &g_Vxi[kabs * NX + n0 + q * 4], nsz);
    }
    CPA_COMMIT();

    for (int c = 0; c < 4; c++) {
        if (c < 3) {
            int buf = (c + 1) & 1;
            if (tid < 128) {
                int kk = tid >> 4, q = tid & 15;
                int kabs = (c + 1) * 8 + kk;
                int msz = (q < mlim) ? 16 : 0;
                int nsz = (q < nlim) ? 16 : 0;
                size_t obY = ((size_t)bo * KM + kabs) * NX + n0 + q * 4;
                size_t obX = ((size_t)bo * KM + kabs) * MY + m0 + q * 4;
                cpa16(&sVyr[buf][kk][q], &g_Vyr[kabs * MY + m0 + q * 4], msz);
                cpa16(&sVyi[buf][kk][q], &g_Vyi[kabs * MY + m0 + q * 4], msz);
                cpa16(&sOxr[buf][kk][q], &g_oxr[obX], msz);
                cpa16(&sOxi[buf][kk][q], &g_oxi[obX], msz);
                cpa16(&sOyr[buf][kk][q], &g_oyr[obY], nsz);
                cpa16(&sOyi[buf][kk][q], &g_oyi[obY], nsz);
                cpa16(&sVxr[buf][kk][q], &g_Vxr[kabs * NX + n0 + q * 4], nsz);
                cpa16(&sVxi[buf][kk][q], &g_Vxi[kabs * NX + n0 + q * 4], nsz);
            }
            CPA_COMMIT();
            CPA_WAIT1();
        } else {
            CPA_WAIT0();
        }
        __syncthreads();

        int cur = c & 1;
#pragma unroll
        for (int j = 0; j < 8; j++) {
            float4 vyr4 = sVyr[cur][j][mg], vyi4 = sVyi[cur][j][mg];
            float4 oxr4 = sOxr[cur][j][mg], oxi4 = sOxi[cur][j][mg];
            float4 oyr4 = sOyr[cur][j][ng], oyi4 = sOyi[cur][j][ng];
            float4 vxr4 = sVxr[cur][j][ng], vxi4 = sVxi[cur][j][ng];
            float vyr[4] = {vyr4.x, vyr4.y, vyr4.z, vyr4.w};
            float vyi[4] = {vyi4.x, vyi4.y, vyi4.z, vyi4.w};
            float oxr[4] = {oxr4.x, oxr4.y, oxr4.z, oxr4.w};
            float oxi[4] = {oxi4.x, oxi4.y, oxi4.z, oxi4.w};
            float oyr[4] = {oyr4.x, oyr4.y, oyr4.z, oyr4.w};
            float oyi[4] = {oyi4.x, oyi4.y, oyi4.z, oyi4.w};
            float vxr[4] = {vxr4.x, vxr4.y, vxr4.z, vxr4.w};
            float vxi[4] = {vxi4.x, vxi4.y, vxi4.z, vxi4.w};
#pragma unroll
            for (int a = 0; a < 4; a++)
#pragma unroll
                for (int q2 = 0; q2 < 4; q2++) {
                    float s = acc[a][q2];
                    s = fmaf(vyr[a], oyr[q2], s);
                    s = fmaf(vyi[a], oyi[q2], s);
                    s = fmaf(oxr[a], vxr[q2], s);
                    s = fmaf(oxi[a], vxi[q2], s);
                    acc[a][q2] = s;
                }
        }
        __syncthreads();
    }

    if (ng < nlim && mg < mlim) {
        float* xb = g_x1 + (size_t)bo * PLANE;
        int n = n0 + ng * 4;
#pragma unroll
        for (int a = 0; a < 4; a++) {
            int m = m0 + mg * 4 + a;
            *(float4*)&xb[m * NX + n] =
                make_float4(acc[a][0], acc[a][1], acc[a][2], acc[a][3]);
        }
    }
}

// ---------------- pointwise MLP + residual ----------------
__global__ void __launch_bounds__(256) pwK(const float* __restrict__ w1, const float* __restrict__ b1,
                    const float* __restrict__ w2, const float* __restrict__ b2,
                    int applyGelu) {
    __shared__ float sX[32][128];
    __shared__ float sT[32][132];
    __shared__ float sW1[32][32], sW2[32][32];
    __shared__ float sB1[32], sB2[32];
    int tid = threadIdx.x;
    for (int idx = tid; idx < 1024; idx += 256) {
        int o = idx >> 5, c = idx & 31;
        sW1[c][o] = w1[o * 32 + c];
        sW2[c][o] = w2[o * 32 + c];
    }
    if (tid < 32) { sB1[tid] = b1[tid]; sB2[tid] = b2[tid]; }

    int p0 = blockIdx.x * 128;
    {
        int pp = tid & 127, ch = (tid >> 7) * 16;
        int p = p0 + pp;
        int b = p / PLANE, mn = p % PLANE;
        const float* src = g_x1 + ((size_t)b * CW + ch) * PLANE + mn;
#pragma unroll
        for (int cc = 0; cc < 16; cc++) sX[ch + cc][pp] = src[(size_t)cc * PLANE];
    }
    __syncthreads();

    int og = tid >> 5, pg = tid & 31;
    {
        float t[4][4];
#pragma unroll
        for (int a = 0; a < 4; a++) {
            float bb = sB1[og * 4 + a];
#pragma unroll
            for (int j = 0; j < 4; j++) t[a][j] = bb;
        }
#pragma unroll 4
        for (int c = 0; c < 32; c++) {
            float4 x4 = *(const float4*)&sX[c][pg * 4];
            float xv[4] = {x4.x, x4.y, x4.z, x4.w};
            float4 w4 = *(const float4*)&sW1[c][og * 4];
            float wv[4] = {w4.x, w4.y, w4.z, w4.w};
#pragma unroll
            for (int a = 0; a < 4; a++)
#pragma unroll
                for (int j = 0; j < 4; j++) t[a][j] = fmaf(wv[a], xv[j], t[a][j]);
        }
#pragma unroll
        for (int a = 0; a < 4; a++)
            *(float4*)&sT[og * 4 + a][pg * 4] =
                make_float4(geluf(t[a][0]), geluf(t[a][1]), geluf(t[a][2]), geluf(t[a][3]));
    }
    __syncthreads();
    {
        float t[4][4];
#pragma unroll
        for (int a = 0; a < 4; a++) {
            float bb = sB2[og * 4 + a];
#pragma unroll
            for (int j = 0; j < 4; j++) t[a][j] = bb;
        }
#pragma unroll 4
        for (int c = 0; c < 32; c++) {
            float4 x4 = *(const float4*)&sT[c][pg * 4];
            float xv[4] = {x4.x, x4.y, x4.z, x4.w};
            float4 w4 = *(const float4*)&sW2[c][og * 4];
            float wv[4] = {w4.x, w4.y, w4.z, w4.w};
#pragma unroll
            for (int a = 0; a < 4; a++)
#pragma unroll
                for (int j = 0; j < 4; j++) t[a][j] = fmaf(wv[a], xv[j], t[a][j]);
        }
        int pbase = p0 + pg * 4;
#pragma unroll
        for (int a = 0; a < 4; a++) {
            int o = og * 4 + a;
#pragma unroll
            for (int j = 0; j < 4; j++) {
                int p = pbase + j;
                int b = p / PLANE, mn = p % PLANE;
                size_t off = ((size_t)b * CW + o) * PLANE + mn;
                float s = t[a][j];
                if (applyGelu) s = geluf(s);
                g_h[off] += s;
            }
        }
    }
}

// ---------------- final head ----------------
__global__ void __launch_bounds__(256) finalK(const float* __restrict__ fc1w, const float* __restrict__ fc1b,
                       const float* __restrict__ fc2w, const float* __restrict__ fc2b,
                       float* __restrict__ out) {
    __shared__ float sX[32][68];
    __shared__ float sW1h[32][64];
    __shared__ float sT[64][68];
    __shared__ float sw2[128], sb1[128];
    __shared__ float sRed[4][64];
    int tid = threadIdx.x;
    if (tid < 128) { sw2[tid] = fc2w[tid]; sb1[tid] = fc1b[tid]; }

    int p0 = blockIdx.x * 64;
    {
        int pp = tid & 63, ch = (tid >> 6) * 8;
        int p = p0 + pp;
        int b = p / PLANE, mn = p % PLANE;
        const float* src = g_h + ((size_t)b * CW + ch) * PLANE + mn;
#pragma unroll
        for (int cc = 0; cc < 8; cc++) sX[ch + cc][pp] = src[(size_t)cc * PLANE];
    }

    float part = 0.f;
    for (int jh = 0; jh < 128; jh += 64) {
        __syncthreads();
        for (int idx = tid; idx < 512; idx += 256) {
            int c = idx >> 4, j4 = idx & 15;
            *(float4*)&sW1h[c][j4 * 4] = *(const float4*)&fc1w[c * 128 + jh + j4 * 4];
        }
        __syncthreads();

        int jg = tid >> 4, pgr = tid & 15;
        float t[4][4];
#pragma unroll
        for (int a = 0; a < 4; a++) {
            float bb = sb1[jh + jg * 4 + a];
#pragma unroll
            for (int j = 0; j < 4; j++) t[a][j] = bb;
        }
#pragma unroll 4
        for (int c = 0; c < 32; c++) {
            float4 x4 = *(const float4*)&sX[c][pgr * 4];
            float xv[4] = {x4.x, x4.y, x4.z, x4.w};
            float4 w4 = *(const float4*)&sW1h[c][jg * 4];
            float wv[4] = {w4.x, w4.y, w4.z, w4.w};
#pragma unroll
            for (int a = 0; a < 4; a++)
#pragma unroll
                for (int j = 0; j < 4; j++) t[a][j] = fmaf(wv[a], xv[j], t[a][j]);
        }
#pragma unroll
        for (int a = 0; a < 4; a++)
            *(float4*)&sT[jg * 4 + a][pgr * 4] =
                make_float4(geluf(t[a][0]), geluf(t[a][1]), geluf(t[a][2]), geluf(t[a][3]));
        __syncthreads();
        {
            int pq = tid & 63, jq = tid >> 6;
            float s = 0.f;
#pragma unroll
            for (int jj = 0; jj < 16; jj++) {
                int j = jq * 16 + jj;
                s = fmaf(sw2[jh + j], sT[j][pq], s);
            }
            part += s;
        }
    }
    __syncthreads();
    {
        int pq = tid & 63, jq = tid >> 6;
        sRed[jq][pq] = part;
    }
    __syncthreads();
    if (tid < 64) {
        out[p0 + tid] = sRed[0][tid] + sRed[1][tid] + sRed[2][tid] + sRed[3][tid] + fc2b[0];
    }
}

// ---------------- launch ----------------
extern "C" void kernel_launch(void* const* d_in, const int* in_sizes, int n_in,
                              void* d_out, int out_size) {
    (void)in_sizes; (void)n_in; (void)out_size;
    const float* x    = (const float*)d_in[0];
    const float* sx   = (const float*)d_in[1];
    const float* sy   = (const float*)d_in[2];
    const float* fc0w = (const float*)d_in[3];
    const float* fc0b = (const float*)d_in[4];
    const float* fw1  = (const float*)d_in[5];
    const float* fw2  = (const float*)d_in[6];
    const float* w1   = (const float*)d_in[7];
    const float* b1   = (const float*)d_in[8];
    const float* w2   = (const float*)d_in[9];
    const float* b2   = (const float*)d_in[10];
    const float* fc1w = (const float*)d_in[11];
    const float* fc1b = (const float*)d_in[12];
    const float* fc2w = (const float*)d_in[13];
    const float* fc2b = (const float*)d_in[14];
    float* out = (float*)d_out;

    precomputeK<<<128, 256>>>(sx, sy);
    fc0K<<<PIX / 128, 256>>>(x, fc0w, fc0b);

    for (int blk = 0; blk < 4; blk++) {
        const float* fw1p = fw1 + (size_t)blk * CW * CW * KM * 2;
        const float* fw2p = fw2 + (size_t)blk * CW * CW * KM * 2;
        const float* w1p  = w1 + (size_t)blk * CW * CW;
        const float* b1p  = b1 + (size_t)blk * CW;
        const float* w2p  = w2 + (size_t)blk * CW * CW;
        const float* b2p  = b2 + (size_t)blk * CW;

        ftK<<<dim3(5, BSZ * CW), 256>>>();
        mixFK<<<dim3(5, KM, BSZ), 256>>>(fw1p, fw2p);
        invK<<<dim3(6, 3, BSZ * CW), 256>>>();
        pwK<<<PIX / 128, 256>>>(w1p, b1p, w2p, b2p, blk < 3 ? 1 : 0);
    }

    finalK<<<PIX / 64, 256>>>(fc1w, fc1b, fc2w, fc2b, out);
}